// round 15
// baseline (speedup 1.0000x reference)
#include <cuda_runtime.h>
#include <cstdint>

using u64 = unsigned long long;

// Problem constants
constexpr int B_ = 16, C_ = 128, H_ = 72, W_ = 200, K_ = 9;
constexpr int CS = H_ * W_;
constexpr int NCIP = 64;                  // ci pairs
constexpr int NR = NCIP * K_;             // 576 weight rows
constexpr int QW_W = W_ + 8;              // 208 (4-halo each side)
constexpr int QW_H = H_ + 8;              // 80
constexpr int RSTR_W = NCIP * QW_W;       // 13312 u64 per row
constexpr int RSTR_H = NCIP * QW_H;       // 5120 u64 per row

// Persistent paired-with-halo buffers + per-slice weight images
__device__ __align__(16) u64 g_pw[(size_t)B_ * H_ * RSTR_W];
__device__ __align__(16) u64 g_ph[(size_t)B_ * W_ * RSTR_H];
__device__ __align__(16) u64 g_ws[4 * 8 * NR * 16];            // [dir][slice][r][16co]

// ---------------- helpers ----------------
__device__ __forceinline__ uint32_t smem_u32(const void* p) {
    uint32_t a;
    asm("{ .reg .u64 t; cvta.to.shared.u64 t, %1; cvt.u32.u64 %0, t; }" : "=r"(a) : "l"(p));
    return a;
}
__device__ __forceinline__ void fma2(u64& d, u64 a, u64 b) {
    asm("fma.rn.f32x2 %0, %1, %2, %0;" : "+l"(d) : "l"(a), "l"(b));
}
__device__ __forceinline__ u64 add2(u64 a, u64 b) {
    u64 r; asm("add.rn.f32x2 %0, %1, %2;" : "=l"(r) : "l"(a), "l"(b)); return r;
}
__device__ __forceinline__ u64 pack2(float a, float b) {
    u64 r; asm("mov.b64 %0, {%1, %2};" : "=l"(r) : "f"(a), "f"(b)); return r;
}
__device__ __forceinline__ void unpack2(u64 v, float& x, float& y) {
    asm("mov.b64 {%0, %1}, %2;" : "=f"(x), "=f"(y) : "l"(v));
}
#define MBAR_INIT(a, n) \
    asm volatile("mbarrier.init.shared.b64 [%0], %1;" :: "r"(a), "r"(n) : "memory")
#define MBAR_EXPECT_TX(a, n) \
    asm volatile("mbarrier.arrive.expect_tx.shared.b64 _, [%0], %1;" :: "r"(a), "r"(n) : "memory")
#define MBAR_WAIT(a, ph) do { \
    asm volatile("{\n\t.reg .pred P;\n\tWL_%=:\n\t" \
        "mbarrier.try_wait.parity.acquire.cta.shared::cta.b64 P, [%0], %1, 0x989680;\n\t" \
        "@P bra.uni WD_%=;\n\tbra.uni WL_%=;\n\tWD_%=:\n\t}" \
        :: "r"(a), "r"(ph) : "memory"); } while (0)
__device__ __forceinline__ void bulk_cp(uint32_t dst, const void* src, uint32_t bytes,
                                        uint32_t mbar) {
    asm volatile(
        "cp.async.bulk.shared::cluster.global.mbarrier::complete_tx::bytes [%0], [%1], %2, [%3];"
        :: "r"(dst), "l"(src), "r"(bytes), "r"(mbar) : "memory");
}
__device__ __forceinline__ void cluster_barrier() {
    asm volatile("barrier.cluster.arrive.aligned;" ::: "memory");
    asm volatile("barrier.cluster.wait.aligned;" ::: "memory");
}

// ---------------- weight prep ----------------
__global__ void prep_weights(const float* w0, const float* w1,
                             const float* w2, const float* w3) {
    const float* ws[4] = {w0, w1, w2, w3};
    const int tot = 4 * 8 * NR * 16;
    for (int i = blockIdx.x * blockDim.x + threadIdx.x; i < tot;
         i += gridDim.x * blockDim.x) {
        int c = i & 15;
        int r = (i >> 4) % NR;
        int slice = (i / (16 * NR)) & 7;
        int d = i / (16 * NR * 8);
        int co = slice * 16 + c;
        int cip = r / K_, k = r % K_;
        const float* w = ws[d];
        g_ws[i] = pack2(w[(size_t)co * (C_ * K_) + (2 * cip) * K_ + k],
                        w[(size_t)co * (C_ * K_) + (2 * cip + 1) * K_ + k]);
    }
}

// ---------------- layout conversions ----------------
__global__ void conv_in(const float* __restrict__ x) {
    const size_t tot = (size_t)B_ * H_ * RSTR_W;
    for (size_t i = (size_t)blockIdx.x * blockDim.x + threadIdx.x; i < tot;
         i += (size_t)gridDim.x * blockDim.x) {
        int q = (int)(i % QW_W);
        size_t r = i / QW_W;
        int cip = (int)(r % NCIP);
        size_t r2 = r / NCIP;
        int h = (int)(r2 % H_);
        int b = (int)(r2 / H_);
        int j = q - 4;
        u64 v = 0;
        if (j >= 0 && j < W_) {
            size_t base = ((size_t)b * C_ + 2 * cip) * CS + (size_t)h * W_ + j;
            v = pack2(x[base], x[base + CS]);
        }
        g_pw[i] = v;
    }
}

__global__ void zero_ph_halo() {
    const int tot = B_ * W_ * NCIP;
    for (int i = blockIdx.x * blockDim.x + threadIdx.x; i < tot;
         i += gridDim.x * blockDim.x) {
        u64* p = g_ph + (size_t)i * QW_H;
        #pragma unroll
        for (int q = 0; q < 4; ++q) { p[q] = 0; p[QW_H - 4 + q] = 0; }
    }
}

__global__ void conv_wh() {
    __shared__ u64 tile[32][33];
    const int slab = blockIdx.z;
    const int cip = slab & 63, b = slab >> 6;
    const int w0 = blockIdx.x * 32, h0 = blockIdx.y * 32;
    #pragma unroll
    for (int i = 0; i < 32; i += 8) {
        int h = h0 + threadIdx.y + i, w = w0 + threadIdx.x;
        if (h < H_ && w < W_)
            tile[threadIdx.y + i][threadIdx.x] =
                g_pw[(size_t)(b * H_ + h) * RSTR_W + cip * QW_W + 4 + w];
    }
    __syncthreads();
    #pragma unroll
    for (int i = 0; i < 32; i += 8) {
        int w = w0 + threadIdx.y + i, h = h0 + threadIdx.x;
        if (h < H_ && w < W_)
            g_ph[(size_t)(b * W_ + w) * RSTR_H + cip * QW_H + 4 + h] =
                tile[threadIdx.x][threadIdx.y + i];
    }
}

__global__ void conv_out(float* __restrict__ out) {
    __shared__ u64 tile[32][33];
    const int slab = blockIdx.z;
    const int cip = slab & 63, b = slab >> 6;
    const int h0 = blockIdx.x * 32, w0 = blockIdx.y * 32;
    #pragma unroll
    for (int i = 0; i < 32; i += 8) {
        int w = w0 + threadIdx.y + i, h = h0 + threadIdx.x;
        if (h < H_ && w < W_)
            tile[threadIdx.y + i][threadIdx.x] =
                g_ph[(size_t)(b * W_ + w) * RSTR_H + cip * QW_H + 4 + h];
    }
    __syncthreads();
    #pragma unroll
    for (int i = 0; i < 32; i += 8) {
        int h = h0 + threadIdx.y + i, w = w0 + threadIdx.x;
        if (h < H_ && w < W_) {
            float lo, hi;
            unpack2(tile[threadIdx.x][threadIdx.y + i], lo, hi);
            size_t base = ((size_t)b * C_ + 2 * cip) * CS + (size_t)h * W_ + w;
            out[base] = lo;
            out[base + CS] = hi;
        }
    }
}

// ---------------- persistent pass kernel ----------------
// Cluster of 8 CTAs = one image. Weights staged ONCE per direction.
// Each step: TMA bulk-copy prev row -> smem, compute (split-cip halves,
// R14 loop), STG cur slice, gpu fence + cluster barrier.
template <int L, int JT, int NT>
__global__ void __launch_bounds__(NT, 1) __cluster_dims__(8, 1, 1)
pass_pk(u64* __restrict__ buf, const u64* __restrict__ wA,
        const u64* __restrict__ wB, int nrows) {
    constexpr int QW = L + 8;
    constexpr int RSTR = NCIP * QW;
    constexpr int NH = NT / 2;
    constexpr int NJG = L / JT;
    static_assert(NH == NJG * 8, "thread map mismatch");

    extern __shared__ __align__(16) u64 sm[];
    u64* w_s = sm;                         // [576][16]
    u64* p_s = sm + NR * 16;               // [64][QW]
    u64* red = p_s + NCIP * QW;            // [NH][2*JT]
    const uint32_t mb_w = smem_u32(red + NH * 2 * JT);
    const uint32_t mb_p = mb_w + 8;

    const int t = threadIdx.x;
    const int slice = blockIdx.x;          // cluster rank
    const int b = blockIdx.y;
    u64* rowb = buf + (size_t)b * nrows * RSTR;

    const int half = (t >= NH);
    const int tt = half ? t - NH : t;
    const int cog = tt & 7;
    const int jg = tt >> 3;
    const int j0 = jg * JT;

    if (t == 0) { MBAR_INIT(mb_w, 1); MBAR_INIT(mb_p, 1); }
    __syncthreads();

    int wph = 0, pph = 0;

    for (int dir = 0; dir < 2; ++dir) {
        // stage this slice's weights once per direction
        if (t == 0) {
            MBAR_EXPECT_TX(mb_w, (uint32_t)(NR * 16 * 8));
            bulk_cp(smem_u32(w_s),
                    (dir ? wB : wA) + (size_t)slice * NR * 16, NR * 16 * 8, mb_w);
        }
        MBAR_WAIT(mb_w, wph); wph ^= 1;

        for (int s = 1; s < nrows; ++s) {
            const int cur = dir ? (nrows - 1 - s) : s;
            const int prev = dir ? (cur + 1) : (cur - 1);

            // TMA restage of prev row (peers' stores visible via barrier below)
            if (t == 0) {
                MBAR_EXPECT_TX(mb_p, (uint32_t)(RSTR * 8));
                bulk_cp(smem_u32(p_s), rowb + (size_t)prev * RSTR, RSTR * 8, mb_p);
            }

            u64* crow = rowb + (size_t)cur * RSTR + (slice * 8 + cog) * QW + 4 + j0;
            u64 xv[JT];
            if (!half) {
                #pragma unroll
                for (int n = 0; n < JT; ++n) xv[n] = crow[n];
            }

            MBAR_WAIT(mb_p, pph); pph ^= 1;

            u64 acc0[JT], acc1[JT];
            #pragma unroll
            for (int n = 0; n < JT; ++n) { acc0[n] = 0ull; acc1[n] = 0ull; }

            const u64* pw = p_s + (half ? 32 * QW : 0) + j0;
            const u64* wc = w_s + (half ? 32 * K_ * 16 : 0) + 2 * cog;

            #pragma unroll 1
            for (int cip = 0; cip < 32; ++cip) {
                u64 win[JT + 8];
                #pragma unroll
                for (int q = 0; q < JT + 8; ++q) win[q] = pw[q];
                #pragma unroll
                for (int k = 0; k < K_; ++k) {
                    const ulonglong2 wp = *(const ulonglong2*)(wc + k * 16);
                    #pragma unroll
                    for (int n = 0; n < JT; ++n) {
                        fma2(acc0[n], wp.x, win[k + n]);
                        fma2(acc1[n], wp.y, win[k + n]);
                    }
                }
                pw += QW;
                wc += K_ * 16;
            }

            if (half) {
                u64* rd = red + (size_t)tt * (2 * JT);
                #pragma unroll
                for (int n = 0; n < JT; ++n) { rd[n] = acc0[n]; rd[JT + n] = acc1[n]; }
            }
            __syncthreads();
            if (!half) {
                const u64* rd = red + (size_t)tt * (2 * JT);
                #pragma unroll
                for (int n = 0; n < JT; ++n) {
                    u64 a0 = add2(acc0[n], rd[n]);
                    u64 a1 = add2(acc1[n], rd[JT + n]);
                    float x0, y0, x1, y1, vx, vy;
                    unpack2(a0, x0, y0);
                    unpack2(a1, x1, y1);
                    unpack2(xv[n], vx, vy);
                    crow[n] = pack2(vx + fmaxf(x0 + y0, 0.f),
                                    vy + fmaxf(x1 + y1, 0.f));
                }
            }

            // make our STGs visible to peer TMA reads, then cluster-sync
            asm volatile("fence.acq_rel.gpu;" ::: "memory");
            cluster_barrier();
        }
    }
}

// W pass: JT=5, NT=640 (2 halves x 40jg x 8cog; 20 warps, 5/SMSP)
// H pass: JT=3, NT=384 (2 halves x 24jg x 8cog; 12 warps, 3/SMSP)
constexpr int SMEM_W = (NR * 16 + NCIP * QW_W + 320 * 10) * 8 + 16;  // 205,840
constexpr int SMEM_H = (NR * 16 + NCIP * QW_H + 192 * 6) * 8 + 16;   // 123,920
static_assert(SMEM_W <= 227 * 1024, "smem W over limit");
static_assert(SMEM_H <= 227 * 1024, "smem H over limit");

extern "C" void kernel_launch(void* const* d_in, const int* in_sizes, int n_in,
                              void* d_out, int out_size) {
    const float* x  = (const float*)d_in[0];
    const float* wd = (const float*)d_in[1];
    const float* wu = (const float*)d_in[2];
    const float* wr = (const float*)d_in[3];
    const float* wl = (const float*)d_in[4];
    float* out = (float*)d_out;

    // one-time setup on the (uncaptured) correctness call only
    static u64* pw = nullptr;
    static u64* ph = nullptr;
    static u64* ws = nullptr;
    static bool init_done = false;
    if (!init_done) {
        cudaGetSymbolAddress((void**)&pw, g_pw);
        cudaGetSymbolAddress((void**)&ph, g_ph);
        cudaGetSymbolAddress((void**)&ws, g_ws);
        cudaFuncSetAttribute((const void*)pass_pk<W_, 5, 640>,
                             cudaFuncAttributeMaxDynamicSharedMemorySize, SMEM_W);
        cudaFuncSetAttribute((const void*)pass_pk<H_, 3, 384>,
                             cudaFuncAttributeMaxDynamicSharedMemorySize, SMEM_H);
        init_done = true;
    }

    prep_weights<<<256, 256>>>(wd, wu, wr, wl);
    conv_in<<<2048, 256>>>(x);

    const size_t DSTR = (size_t)8 * NR * 16;   // per-direction weight stride
    const dim3 grid(8, 16);

    // down + up: conv along W, scan over H (persistent, weights staged 2x)
    pass_pk<W_, 5, 640><<<grid, 640, SMEM_W>>>(pw, ws + 0 * DSTR, ws + 1 * DSTR, H_);

    // PW -> PH (transpose)
    zero_ph_halo<<<512, 256>>>();
    conv_wh<<<dim3(7, 3, B_ * NCIP), dim3(32, 8)>>>();

    // right + left: conv along H, scan over W (persistent)
    pass_pk<H_, 3, 384><<<grid, 384, SMEM_H>>>(ph, ws + 2 * DSTR, ws + 3 * DSTR, W_);

    // PH -> out
    conv_out<<<dim3(3, 7, B_ * NCIP), dim3(32, 8)>>>(out);
}

// round 16
// speedup vs baseline: 3.3462x; 3.3462x over previous
#include <cuda_runtime.h>
#include <cuda_bf16.h>
#include <cstdint>

using u64 = unsigned long long;
using u32 = uint32_t;
using u8 = unsigned char;

// Problem constants
constexpr int B_ = 16, C_ = 128, H_ = 72, W_ = 200, K_ = 9;

// P-plane geometry (bf16, row = spatial pos with 4-halo, 136 cols *2B = 272B row)
constexpr int RB = 272;                     // row bytes
constexpr int ROWS_W = 232;                 // j rows: 4 halo + 200 + 28 pad (M=224 cover +8 tap)
constexpr int ROWS_H = 104;                 // h rows: 4 + 72 + 28
constexpr int PPB_W = ROWS_W * RB;          // 63,104
constexpr int PPB_H = ROWS_H * RB;          // 28,288
constexpr int PAIR_W = 2 * PPB_W;           // hi + lo planes
constexpr int PAIR_H = 2 * PPB_H;
constexpr int WTB = 2 * 9 * 128 * 32;       // per-slice weight block: [part][tap][ci][16co*2B]

// Device globals (no allocs allowed)
__device__ __align__(16) u8 g_pbw[(size_t)B_ * H_ * PAIR_W];
__device__ __align__(16) u8 g_pbh[(size_t)B_ * W_ * PAIR_H];
__device__ __align__(16) u8 g_wt[4 * 8 * WTB];
__device__ float g_fw[(size_t)B_ * H_ * W_ * C_];   // [b][h][j][co]
__device__ float g_fh[(size_t)B_ * W_ * H_ * C_];   // [b][w][h][co]

// ---------------- low-level helpers ----------------
__device__ __forceinline__ u32 smem_u32(const void* p) {
    u32 a;
    asm("{ .reg .u64 t; cvta.to.shared.u64 t, %1; cvt.u32.u64 %0, t; }" : "=r"(a) : "l"(p));
    return a;
}
#define MBAR_INIT(a, n) \
    asm volatile("mbarrier.init.shared.b64 [%0], %1;" :: "r"(a), "r"(n) : "memory")
#define MBAR_EXPECT_TX(a, n) \
    asm volatile("mbarrier.arrive.expect_tx.shared.b64 _, [%0], %1;" :: "r"(a), "r"(n) : "memory")
#define MBAR_WAIT(a, ph) do { \
    asm volatile("{\n\t.reg .pred P;\n\tWL_%=:\n\t" \
        "mbarrier.try_wait.parity.acquire.cta.shared::cta.b64 P, [%0], %1, 0x989680;\n\t" \
        "@P bra.uni WD_%=;\n\tbra.uni WL_%=;\n\tWD_%=:\n\t}" \
        :: "r"(a), "r"(ph) : "memory"); } while (0)
__device__ __forceinline__ void bulk_cp(u32 dst, const void* src, u32 bytes, u32 mbar) {
    asm volatile(
        "cp.async.bulk.shared::cluster.global.mbarrier::complete_tx::bytes [%0], [%1], %2, [%3];"
        :: "r"(dst), "l"(src), "r"(bytes), "r"(mbar) : "memory");
}
__device__ __forceinline__ void ldm_x4(u32* r, u32 a) {
    asm volatile("ldmatrix.sync.aligned.m8n8.x4.shared.b16 {%0,%1,%2,%3}, [%4];"
        : "=r"(r[0]), "=r"(r[1]), "=r"(r[2]), "=r"(r[3]) : "r"(a));
}
__device__ __forceinline__ void ldm_x4t(u32* r, u32 a) {
    asm volatile("ldmatrix.sync.aligned.m8n8.x4.trans.shared.b16 {%0,%1,%2,%3}, [%4];"
        : "=r"(r[0]), "=r"(r[1]), "=r"(r[2]), "=r"(r[3]) : "r"(a));
}
__device__ __forceinline__ void mma16816(float* d, const u32* a, const u32* b) {
    asm volatile(
        "mma.sync.aligned.m16n8k16.row.col.f32.bf16.bf16.f32 "
        "{%0,%1,%2,%3}, {%4,%5,%6,%7}, {%8,%9}, {%0,%1,%2,%3};"
        : "+f"(d[0]), "+f"(d[1]), "+f"(d[2]), "+f"(d[3])
        : "r"(a[0]), "r"(a[1]), "r"(a[2]), "r"(a[3]), "r"(b[0]), "r"(b[1]));
}
__device__ __forceinline__ u32 pack_bf(float v0, float v1) {   // lower 16 = v0
    u32 r; asm("cvt.rn.bf16x2.f32 %0, %1, %2;" : "=r"(r) : "f"(v1), "f"(v0)); return r;
}

// ---------------- weight prep ----------------
// WT[d][slice][part][tap][ci][co16]: B matrix per tap, k(ci)-major rows, 32B/row
__global__ void prep_weights(const float* w0, const float* w1,
                             const float* w2, const float* w3) {
    const float* ws[4] = {w0, w1, w2, w3};
    const int tot = 4 * 8 * 2 * 9 * 128 * 16;
    for (int i = blockIdx.x * blockDim.x + threadIdx.x; i < tot;
         i += gridDim.x * blockDim.x) {
        int co = i & 15;
        int ci = (i >> 4) & 127;
        int tap = (i >> 11) % 9;
        int part = (i / (2048 * 9)) & 1;
        int slice = (i / (2048 * 9 * 2)) & 7;
        int d = i / (2048 * 9 * 2 * 8);
        float v = ws[d][(size_t)(slice * 16 + co) * (C_ * K_) + ci * K_ + tap];
        __nv_bfloat16 hi = __float2bfloat16(v);
        __nv_bfloat16 out = part ? __float2bfloat16(v - __bfloat162float(hi)) : hi;
        size_t off = ((((size_t)(d * 8 + slice) * 2 + part) * 9 + tap) * 128 + ci) * 32
                     + co * 2;
        *(__nv_bfloat16*)(g_wt + off) = out;
    }
}

// ---------------- zero halo/pad rows of all P planes ----------------
__global__ void zero_pads() {
    // W: planes 16*72*2 parts, pad rows p: p<4 ? p : 200+p (4..31 -> 204..231)
    const int totw = B_ * H_ * 2 * 32 * (RB / 4);
    for (int i = blockIdx.x * blockDim.x + threadIdx.x; i < totw;
         i += gridDim.x * blockDim.x) {
        int q = i % (RB / 4);
        int p = (i / (RB / 4)) % 32;
        int pp = i / ((RB / 4) * 32);      // plane-part index
        int row = p < 4 ? p : 200 + p;
        *(u32*)(g_pbw + (size_t)pp * PPB_W + row * RB + q * 4) = 0;
    }
    const int toth = B_ * W_ * 2 * 32 * (RB / 4);
    for (int i = blockIdx.x * blockDim.x + threadIdx.x; i < toth;
         i += gridDim.x * blockDim.x) {
        int q = i % (RB / 4);
        int p = (i / (RB / 4)) % 32;
        int pp = i / ((RB / 4) * 32);
        int row = p < 4 ? p : 72 + p;
        *(u32*)(g_pbh + (size_t)pp * PPB_H + row * RB + q * 4) = 0;
    }
}

// ---------------- conv_in: x (B,C,H,W) -> F_W [b][h][j][co] + PB_W plane 0 ----------------
__global__ void conv_in(const float* __restrict__ x) {
    __shared__ float tile[32][33];
    const int bh = blockIdx.z;               // b*72 + h
    const int b = bh / H_, h = bh % H_;
    const int j0 = blockIdx.x * 32, c0 = blockIdx.y * 32;
    #pragma unroll
    for (int i = 0; i < 32; i += 8) {
        int c = c0 + threadIdx.y + i, j = j0 + threadIdx.x;
        if (c < C_ && j < W_)
            tile[threadIdx.y + i][threadIdx.x] =
                x[((size_t)(b * C_ + c) * H_ + h) * W_ + j];
    }
    __syncthreads();
    #pragma unroll
    for (int i = 0; i < 32; i += 8) {
        int j = j0 + threadIdx.y + i, c = c0 + threadIdx.x;
        if (c < C_ && j < W_) {
            float v = tile[threadIdx.x][threadIdx.y + i];
            g_fw[((size_t)bh * W_ + j) * C_ + c] = v;
            if (h == 0) {
                u8* pl = g_pbw + (size_t)(b * H_) * PAIR_W;   // plane (b, 0)
                __nv_bfloat16 hi = __float2bfloat16(v);
                *(__nv_bfloat16*)(pl + (j + 4) * RB + c * 2) = hi;
                *(__nv_bfloat16*)(pl + PPB_W + (j + 4) * RB + c * 2) =
                    __float2bfloat16(v - __bfloat162float(hi));
            }
        }
    }
}

// ---------------- transition: F_W -> F_H + PB_H plane 0 ----------------
__global__ void transition() {
    const int bh = blockIdx.x;               // b*72 + h
    const int b = bh / H_, h = bh % H_;
    for (int i = threadIdx.x; i < W_ * C_; i += blockDim.x) {
        int j = i / C_, c = i % C_;
        float v = g_fw[((size_t)bh * W_ + j) * C_ + c];
        g_fh[((size_t)(b * W_ + j) * H_ + h) * C_ + c] = v;
        if (j == 0) {
            u8* pl = g_pbh + (size_t)(b * W_) * PAIR_H;       // plane (b, 0)
            __nv_bfloat16 hi = __float2bfloat16(v);
            *(__nv_bfloat16*)(pl + (h + 4) * RB + c * 2) = hi;
            *(__nv_bfloat16*)(pl + PPB_H + (h + 4) * RB + c * 2) =
                __float2bfloat16(v - __bfloat162float(hi));
        }
    }
}

// ---------------- conv_out: F_H -> out (B,C,H,W) ----------------
__global__ void conv_out(float* __restrict__ out) {
    __shared__ float tile[32][33];
    const int bh = blockIdx.z;
    const int b = bh / H_, h = bh % H_;
    const int w0 = blockIdx.x * 32, c0 = blockIdx.y * 32;
    #pragma unroll
    for (int i = 0; i < 32; i += 8) {
        int w = w0 + threadIdx.y + i, c = c0 + threadIdx.x;
        if (c < C_ && w < W_)
            tile[threadIdx.y + i][threadIdx.x] =
                g_fh[((size_t)(b * W_ + w) * H_ + h) * C_ + c];
    }
    __syncthreads();
    #pragma unroll
    for (int i = 0; i < 32; i += 8) {
        int c = c0 + threadIdx.y + i, w = w0 + threadIdx.x;
        if (c < C_ && w < W_)
            out[((size_t)(b * C_ + c) * H_ + h) * W_ + w] =
                tile[threadIdx.x][threadIdx.y + i];
    }
}

// ---------------- HMMA scan step ----------------
// D[j, co] = sum_{tap,ci} P[j+tap-4][ci] * W_tap[ci][co]; then
// F[cur] += relu(D), and bf16 hi/lo of the result written to PB plane 'cur'.
// Warp = m32 x n16 (2 M-tiles x 2 N-tiles). A rows shifted per tap.
template <int L, int ROWS, int NP, int MW, int NT>
__global__ void __launch_bounds__(NT, 1)
step_mma(float* __restrict__ F, u8* __restrict__ PB,
         const u8* __restrict__ WT, int prev, int cur) {
    constexpr int PPB = ROWS * RB;
    constexpr int PAIR = 2 * PPB;
    constexpr int SMT = PAIR + WTB;

    extern __shared__ __align__(16) u8 smem[];
    const u32 sb = smem_u32(smem);
    const u32 mb = sb + SMT;

    const int t = threadIdx.x;
    const int lane = t & 31, w = t >> 5;
    const int g = lane >> 2, tq = lane & 3;
    const int slice = blockIdx.x;
    const int b = blockIdx.y;

    if (t == 0) MBAR_INIT(mb, 1);
    __syncthreads();
    if (t == 0) {
        MBAR_EXPECT_TX(mb, (u32)(PAIR + WTB));
        bulk_cp(sb, PB + (size_t)(b * NP + prev) * PAIR, PAIR, mb);
        bulk_cp(sb + PAIR, WT + (size_t)slice * WTB, WTB, mb);
    }
    if (w >= MW) return;

    const int Mb = w * 32;

    // prefetch cur-row base values (this pass's "+x" term)
    float2 xv[2][2][2];
    #pragma unroll
    for (int mt = 0; mt < 2; ++mt)
        #pragma unroll
        for (int nt = 0; nt < 2; ++nt)
            #pragma unroll
            for (int ri = 0; ri < 2; ++ri) {
                int row = Mb + mt * 16 + g + ri * 8;
                xv[mt][nt][ri] = (row < L)
                    ? *(const float2*)(F + ((size_t)(b * NP + cur) * L + row) * C_
                                         + slice * 16 + nt * 8 + tq * 2)
                    : make_float2(0.f, 0.f);
            }

    MBAR_WAIT(mb, 0);

    float D[2][2][4] = {};

    const u32 aAh = sb + (Mb + (lane & 15)) * RB + ((lane >> 4) << 4);
    const u32 aAl = aAh + PPB;
    const u32 aB = sb + PAIR + (lane & 15) * 32 + ((lane >> 4) << 4);
    constexpr u32 WPART = 9 * 128 * 32;   // hi->lo stride in WT block

    #pragma unroll 1
    for (int tap = 0; tap < 9; ++tap) {
        const u32 tA = tap * RB;
        const u32 tB = tap * 4096;
        #pragma unroll
        for (int ks = 0; ks < 8; ++ks) {
            const u32 oA = tA + ks * 32;
            const u32 oB = tB + ks * 512;
            u32 ah0[4], ah1[4], al0[4], al1[4], bh[4], bl[4];
            ldm_x4(ah0, aAh + oA);
            ldm_x4(ah1, aAh + oA + 16 * RB);
            ldm_x4(al0, aAl + oA);
            ldm_x4(al1, aAl + oA + 16 * RB);
            ldm_x4t(bh, aB + oB);
            ldm_x4t(bl, aB + WPART + oB);
            mma16816(D[0][0], ah0, bh);     mma16816(D[0][1], ah0, bh + 2);
            mma16816(D[1][0], ah1, bh);     mma16816(D[1][1], ah1, bh + 2);
            mma16816(D[0][0], al0, bh);     mma16816(D[0][1], al0, bh + 2);
            mma16816(D[1][0], al1, bh);     mma16816(D[1][1], al1, bh + 2);
            mma16816(D[0][0], ah0, bl);     mma16816(D[0][1], ah0, bl + 2);
            mma16816(D[1][0], ah1, bl);     mma16816(D[1][1], ah1, bl + 2);
        }
    }

    // epilogue
    u8* PBc = PB + (size_t)(b * NP + cur) * PAIR;
    float* Fc = F + (size_t)(b * NP + cur) * L * C_;
    #pragma unroll
    for (int mt = 0; mt < 2; ++mt)
        #pragma unroll
        for (int nt = 0; nt < 2; ++nt) {
            const int co = slice * 16 + nt * 8 + tq * 2;
            #pragma unroll
            for (int ri = 0; ri < 2; ++ri) {
                const int row = Mb + mt * 16 + g + ri * 8;
                if (row < L) {
                    float2 x = xv[mt][nt][ri];
                    float v0 = x.x + fmaxf(D[mt][nt][ri * 2], 0.f);
                    float v1 = x.y + fmaxf(D[mt][nt][ri * 2 + 1], 0.f);
                    *(float2*)(Fc + (size_t)row * C_ + co) = make_float2(v0, v1);
                    __nv_bfloat16 h0 = __float2bfloat16(v0);
                    __nv_bfloat16 h1 = __float2bfloat16(v1);
                    u32 hp = ((u32)__bfloat16_as_ushort(h1) << 16) |
                             __bfloat16_as_ushort(h0);
                    *(u32*)(PBc + (row + 4) * RB + co * 2) = hp;
                    float l0 = v0 - __bfloat162float(h0);
                    float l1 = v1 - __bfloat162float(h1);
                    *(u32*)(PBc + PPB + (row + 4) * RB + co * 2) = pack_bf(l0, l1);
                }
            }
        }
}

constexpr int SMEM_W = PAIR_W + WTB + 16;   // 199,952
constexpr int SMEM_H = PAIR_H + WTB + 16;   // 130,320
static_assert(SMEM_W <= 227 * 1024, "smem W over limit");

extern "C" void kernel_launch(void* const* d_in, const int* in_sizes, int n_in,
                              void* d_out, int out_size) {
    const float* x  = (const float*)d_in[0];
    const float* wd = (const float*)d_in[1];
    const float* wu = (const float*)d_in[2];
    const float* wr = (const float*)d_in[3];
    const float* wl = (const float*)d_in[4];
    float* out = (float*)d_out;

    static u8* pbw = nullptr;
    static u8* pbh = nullptr;
    static u8* wt = nullptr;
    static float* fw = nullptr;
    static float* fh = nullptr;
    static bool init_done = false;
    if (!init_done) {
        cudaGetSymbolAddress((void**)&pbw, g_pbw);
        cudaGetSymbolAddress((void**)&pbh, g_pbh);
        cudaGetSymbolAddress((void**)&wt, g_wt);
        cudaGetSymbolAddress((void**)&fw, g_fw);
        cudaGetSymbolAddress((void**)&fh, g_fh);
        cudaFuncSetAttribute((const void*)step_mma<W_, ROWS_W, H_, 7, 256>,
                             cudaFuncAttributeMaxDynamicSharedMemorySize, SMEM_W);
        cudaFuncSetAttribute((const void*)step_mma<H_, ROWS_H, W_, 3, 128>,
                             cudaFuncAttributeMaxDynamicSharedMemorySize, SMEM_H);
        init_done = true;
    }

    prep_weights<<<512, 256>>>(wd, wu, wr, wl);
    zero_pads<<<1024, 256>>>();
    conv_in<<<dim3(7, 4, B_ * H_), dim3(32, 8)>>>(x);

    const size_t DSTR = (size_t)8 * WTB;     // per-direction weight stride
    const dim3 grid(8, B_);

    // down / up: conv along W, scan over H
    for (int h = 1; h < H_; ++h)
        step_mma<W_, ROWS_W, H_, 7, 256><<<grid, 256, SMEM_W>>>(
            fw, pbw, wt + 0 * DSTR, h - 1, h);
    for (int h = H_ - 2; h >= 0; --h)
        step_mma<W_, ROWS_W, H_, 7, 256><<<grid, 256, SMEM_W>>>(
            fw, pbw, wt + 1 * DSTR, h + 1, h);

    transition<<<B_ * H_, 256>>>();

    // right / left: conv along H, scan over W
    for (int w = 1; w < W_; ++w)
        step_mma<H_, ROWS_H, W_, 3, 128><<<grid, 128, SMEM_H>>>(
            fh, pbh, wt + 2 * DSTR, w - 1, w);
    for (int w = W_ - 2; w >= 0; --w)
        step_mma<H_, ROWS_H, W_, 3, 128><<<grid, 128, SMEM_H>>>(
            fh, pbh, wt + 3 * DSTR, w + 1, w);

    conv_out<<<dim3(7, 4, B_ * H_), dim3(32, 8)>>>(out);
}

// round 17
// speedup vs baseline: 3.4430x; 1.0289x over previous
#include <cuda_runtime.h>
#include <cuda_bf16.h>
#include <cstdint>

using u64 = unsigned long long;
using u32 = uint32_t;
using u8 = unsigned char;

// Problem constants
constexpr int B_ = 16, C_ = 128, H_ = 72, W_ = 200, K_ = 9;

// P-plane geometry (bf16, row = spatial pos with 4-halo, 136 cols *2B = 272B row)
constexpr int RB = 272;                     // row bytes
constexpr int ROWS_W = 232;                 // j rows: 4 halo + 200 + 28 pad
constexpr int ROWS_H = 104;                 // h rows: 4 + 72 + 28
constexpr int PPB_W = ROWS_W * RB;
constexpr int PPB_H = ROWS_H * RB;
constexpr int PAIR_W = 2 * PPB_W;
constexpr int PAIR_H = 2 * PPB_H;
constexpr int WTB = 2 * 9 * 128 * 32;       // per-slice weight block

__device__ __align__(16) u8 g_pbw[(size_t)B_ * H_ * PAIR_W];
__device__ __align__(16) u8 g_pbh[(size_t)B_ * W_ * PAIR_H];
__device__ __align__(16) u8 g_wt[4 * 8 * WTB];
__device__ float g_fw[(size_t)B_ * H_ * W_ * C_];   // [b][h][j][co]
__device__ float g_fh[(size_t)B_ * W_ * H_ * C_];   // [b][w][h][co]

// ---------------- low-level helpers ----------------
__device__ __forceinline__ u32 smem_u32(const void* p) {
    u32 a;
    asm("{ .reg .u64 t; cvta.to.shared.u64 t, %1; cvt.u32.u64 %0, t; }" : "=r"(a) : "l"(p));
    return a;
}
#define MBAR_INIT(a, n) \
    asm volatile("mbarrier.init.shared.b64 [%0], %1;" :: "r"(a), "r"(n) : "memory")
#define MBAR_EXPECT_TX(a, n) \
    asm volatile("mbarrier.arrive.expect_tx.shared.b64 _, [%0], %1;" :: "r"(a), "r"(n) : "memory")
#define MBAR_WAIT(a, ph) do { \
    asm volatile("{\n\t.reg .pred P;\n\tWL_%=:\n\t" \
        "mbarrier.try_wait.parity.acquire.cta.shared::cta.b64 P, [%0], %1, 0x989680;\n\t" \
        "@P bra.uni WD_%=;\n\tbra.uni WL_%=;\n\tWD_%=:\n\t}" \
        :: "r"(a), "r"(ph) : "memory"); } while (0)
__device__ __forceinline__ void bulk_cp(u32 dst, const void* src, u32 bytes, u32 mbar) {
    asm volatile(
        "cp.async.bulk.shared::cluster.global.mbarrier::complete_tx::bytes [%0], [%1], %2, [%3];"
        :: "r"(dst), "l"(src), "r"(bytes), "r"(mbar) : "memory");
}
__device__ __forceinline__ void ldm_x4(u32* r, u32 a) {
    asm volatile("ldmatrix.sync.aligned.m8n8.x4.shared.b16 {%0,%1,%2,%3}, [%4];"
        : "=r"(r[0]), "=r"(r[1]), "=r"(r[2]), "=r"(r[3]) : "r"(a));
}
__device__ __forceinline__ void ldm_x4t(u32* r, u32 a) {
    asm volatile("ldmatrix.sync.aligned.m8n8.x4.trans.shared.b16 {%0,%1,%2,%3}, [%4];"
        : "=r"(r[0]), "=r"(r[1]), "=r"(r[2]), "=r"(r[3]) : "r"(a));
}
__device__ __forceinline__ void mma16816(float* d, const u32* a, const u32* b) {
    asm volatile(
        "mma.sync.aligned.m16n8k16.row.col.f32.bf16.bf16.f32 "
        "{%0,%1,%2,%3}, {%4,%5,%6,%7}, {%8,%9}, {%0,%1,%2,%3};"
        : "+f"(d[0]), "+f"(d[1]), "+f"(d[2]), "+f"(d[3])
        : "r"(a[0]), "r"(a[1]), "r"(a[2]), "r"(a[3]), "r"(b[0]), "r"(b[1]));
}
__device__ __forceinline__ u32 pack_bf(float v0, float v1) {
    u32 r; asm("cvt.rn.bf16x2.f32 %0, %1, %2;" : "=r"(r) : "f"(v1), "f"(v0)); return r;
}

// ---------------- weight prep ----------------
__global__ void prep_weights(const float* w0, const float* w1,
                             const float* w2, const float* w3) {
    const float* ws[4] = {w0, w1, w2, w3};
    const int tot = 4 * 8 * 2 * 9 * 128 * 16;
    for (int i = blockIdx.x * blockDim.x + threadIdx.x; i < tot;
         i += gridDim.x * blockDim.x) {
        int co = i & 15;
        int ci = (i >> 4) & 127;
        int tap = (i >> 11) % 9;
        int part = (i / (2048 * 9)) & 1;
        int slice = (i / (2048 * 9 * 2)) & 7;
        int d = i / (2048 * 9 * 2 * 8);
        float v = ws[d][(size_t)(slice * 16 + co) * (C_ * K_) + ci * K_ + tap];
        __nv_bfloat16 hi = __float2bfloat16(v);
        __nv_bfloat16 out = part ? __float2bfloat16(v - __bfloat162float(hi)) : hi;
        size_t off = ((((size_t)(d * 8 + slice) * 2 + part) * 9 + tap) * 128 + ci) * 32
                     + co * 2;
        *(__nv_bfloat16*)(g_wt + off) = out;
    }
}

// ---------------- zero halo/pad rows ----------------
__global__ void zero_pads() {
    const int totw = B_ * H_ * 2 * 32 * (RB / 4);
    for (int i = blockIdx.x * blockDim.x + threadIdx.x; i < totw;
         i += gridDim.x * blockDim.x) {
        int q = i % (RB / 4);
        int p = (i / (RB / 4)) % 32;
        int pp = i / ((RB / 4) * 32);
        int row = p < 4 ? p : 200 + p;
        *(u32*)(g_pbw + (size_t)pp * PPB_W + row * RB + q * 4) = 0;
    }
    const int toth = B_ * W_ * 2 * 32 * (RB / 4);
    for (int i = blockIdx.x * blockDim.x + threadIdx.x; i < toth;
         i += gridDim.x * blockDim.x) {
        int q = i % (RB / 4);
        int p = (i / (RB / 4)) % 32;
        int pp = i / ((RB / 4) * 32);
        int row = p < 4 ? p : 72 + p;
        *(u32*)(g_pbh + (size_t)pp * PPB_H + row * RB + q * 4) = 0;
    }
}

// ---------------- conv_in ----------------
__global__ void conv_in(const float* __restrict__ x) {
    __shared__ float tile[32][33];
    const int bh = blockIdx.z;
    const int b = bh / H_, h = bh % H_;
    const int j0 = blockIdx.x * 32, c0 = blockIdx.y * 32;
    #pragma unroll
    for (int i = 0; i < 32; i += 8) {
        int c = c0 + threadIdx.y + i, j = j0 + threadIdx.x;
        if (c < C_ && j < W_)
            tile[threadIdx.y + i][threadIdx.x] =
                x[((size_t)(b * C_ + c) * H_ + h) * W_ + j];
    }
    __syncthreads();
    #pragma unroll
    for (int i = 0; i < 32; i += 8) {
        int j = j0 + threadIdx.y + i, c = c0 + threadIdx.x;
        if (c < C_ && j < W_) {
            float v = tile[threadIdx.x][threadIdx.y + i];
            g_fw[((size_t)bh * W_ + j) * C_ + c] = v;
            if (h == 0) {
                u8* pl = g_pbw + (size_t)(b * H_) * PAIR_W;
                __nv_bfloat16 hi = __float2bfloat16(v);
                *(__nv_bfloat16*)(pl + (j + 4) * RB + c * 2) = hi;
                *(__nv_bfloat16*)(pl + PPB_W + (j + 4) * RB + c * 2) =
                    __float2bfloat16(v - __bfloat162float(hi));
            }
        }
    }
}

// ---------------- transition ----------------
__global__ void transition() {
    const int bh = blockIdx.x;
    const int b = bh / H_, h = bh % H_;
    for (int i = threadIdx.x; i < W_ * C_; i += blockDim.x) {
        int j = i / C_, c = i % C_;
        float v = g_fw[((size_t)bh * W_ + j) * C_ + c];
        g_fh[((size_t)(b * W_ + j) * H_ + h) * C_ + c] = v;
        if (j == 0) {
            u8* pl = g_pbh + (size_t)(b * W_) * PAIR_H;
            __nv_bfloat16 hi = __float2bfloat16(v);
            *(__nv_bfloat16*)(pl + (h + 4) * RB + c * 2) = hi;
            *(__nv_bfloat16*)(pl + PPB_H + (h + 4) * RB + c * 2) =
                __float2bfloat16(v - __bfloat162float(hi));
        }
    }
}

// ---------------- conv_out ----------------
__global__ void conv_out(float* __restrict__ out) {
    __shared__ float tile[32][33];
    const int bh = blockIdx.z;
    const int b = bh / H_, h = bh % H_;
    const int w0 = blockIdx.x * 32, c0 = blockIdx.y * 32;
    #pragma unroll
    for (int i = 0; i < 32; i += 8) {
        int w = w0 + threadIdx.y + i, c = c0 + threadIdx.x;
        if (c < C_ && w < W_)
            tile[threadIdx.y + i][threadIdx.x] =
                g_fh[((size_t)(b * W_ + w) * H_ + h) * C_ + c];
    }
    __syncthreads();
    #pragma unroll
    for (int i = 0; i < 32; i += 8) {
        int c = c0 + threadIdx.y + i, w = w0 + threadIdx.x;
        if (c < C_ && w < W_)
            out[((size_t)(b * C_ + c) * H_ + h) * W_ + w] =
                tile[threadIdx.x][threadIdx.y + i];
    }
}

// ---------------- HMMA scan step (software-pipelined) ----------------
template <int L, int ROWS, int NP, int MW, int NT>
__global__ void __launch_bounds__(NT, 1)
step_mma(float* __restrict__ F, u8* __restrict__ PB,
         const u8* __restrict__ WT, int prev, int cur) {
    constexpr int PPB = ROWS * RB;
    constexpr int PAIR = 2 * PPB;
    constexpr int SMT = PAIR + WTB;
    constexpr u32 WPART = 9 * 128 * 32;

    extern __shared__ __align__(16) u8 smem[];
    const u32 sb = smem_u32(smem);
    const u32 mb = sb + SMT;

    const int t = threadIdx.x;
    const int lane = t & 31, w = t >> 5;
    const int g = lane >> 2, tq = lane & 3;
    const int slice = blockIdx.x;
    const int b = blockIdx.y;

    if (t == 0) MBAR_INIT(mb, 1);
    __syncthreads();
    if (t == 0) {
        MBAR_EXPECT_TX(mb, (u32)(PAIR + WTB));
        bulk_cp(sb, PB + (size_t)(b * NP + prev) * PAIR, PAIR, mb);
        bulk_cp(sb + PAIR, WT + (size_t)slice * WTB, WTB, mb);
    }
    if (w >= MW) return;

    const int Mb = w * 32;

    // prefetch cur-row base values
    float2 xv[2][2][2];
    #pragma unroll
    for (int mt = 0; mt < 2; ++mt)
        #pragma unroll
        for (int nt = 0; nt < 2; ++nt)
            #pragma unroll
            for (int ri = 0; ri < 2; ++ri) {
                int row = Mb + mt * 16 + g + ri * 8;
                xv[mt][nt][ri] = (row < L)
                    ? *(const float2*)(F + ((size_t)(b * NP + cur) * L + row) * C_
                                         + slice * 16 + nt * 8 + tq * 2)
                    : make_float2(0.f, 0.f);
            }

    MBAR_WAIT(mb, 0);

    float D[2][2][4] = {};

    const u32 aAh = sb + (Mb + (lane & 15)) * RB + ((lane >> 4) << 4);
    const u32 aAl = aAh + PPB;
    const u32 aB = sb + PAIR + (lane & 15) * 32 + ((lane >> 4) << 4);

    // fragment double-buffer: [buf][ah0 ah1 al0 al1 bh bl] x 4 regs
    u32 fr[2][24];
    auto load_frags = [&](u32* f, int jj) {
        const int tap = jj >> 3, ks = jj & 7;
        const u32 oA = (u32)(tap * RB + ks * 32);
        const u32 oB = (u32)(tap * 4096 + ks * 512);
        ldm_x4(f + 0, aAh + oA);
        ldm_x4(f + 4, aAh + oA + 16 * RB);
        ldm_x4(f + 8, aAl + oA);
        ldm_x4(f + 12, aAl + oA + 16 * RB);
        ldm_x4t(f + 16, aB + oB);
        ldm_x4t(f + 20, aB + WPART + oB);
    };

    load_frags(fr[0], 0);
    #pragma unroll 8
    for (int jj = 0; jj < 72; ++jj) {
        u32* f = fr[jj & 1];
        if (jj < 71) load_frags(fr[(jj & 1) ^ 1], jj + 1);
        const u32 *ah0 = f, *ah1 = f + 4, *al0 = f + 8, *al1 = f + 12;
        const u32 *bh = f + 16, *bl = f + 20;
        mma16816(D[0][0], ah0, bh);     mma16816(D[0][1], ah0, bh + 2);
        mma16816(D[1][0], ah1, bh);     mma16816(D[1][1], ah1, bh + 2);
        mma16816(D[0][0], al0, bh);     mma16816(D[0][1], al0, bh + 2);
        mma16816(D[1][0], al1, bh);     mma16816(D[1][1], al1, bh + 2);
        mma16816(D[0][0], ah0, bl);     mma16816(D[0][1], ah0, bl + 2);
        mma16816(D[1][0], ah1, bl);     mma16816(D[1][1], ah1, bl + 2);
    }

    // epilogue
    u8* PBc = PB + (size_t)(b * NP + cur) * PAIR;
    float* Fc = F + (size_t)(b * NP + cur) * L * C_;
    #pragma unroll
    for (int mt = 0; mt < 2; ++mt)
        #pragma unroll
        for (int nt = 0; nt < 2; ++nt) {
            const int co = slice * 16 + nt * 8 + tq * 2;
            #pragma unroll
            for (int ri = 0; ri < 2; ++ri) {
                const int row = Mb + mt * 16 + g + ri * 8;
                if (row < L) {
                    float2 x = xv[mt][nt][ri];
                    float v0 = x.x + fmaxf(D[mt][nt][ri * 2], 0.f);
                    float v1 = x.y + fmaxf(D[mt][nt][ri * 2 + 1], 0.f);
                    *(float2*)(Fc + (size_t)row * C_ + co) = make_float2(v0, v1);
                    __nv_bfloat16 h0 = __float2bfloat16(v0);
                    __nv_bfloat16 h1 = __float2bfloat16(v1);
                    u32 hp = ((u32)__bfloat16_as_ushort(h1) << 16) |
                             __bfloat16_as_ushort(h0);
                    *(u32*)(PBc + (row + 4) * RB + co * 2) = hp;
                    float l0 = v0 - __bfloat162float(h0);
                    float l1 = v1 - __bfloat162float(h1);
                    *(u32*)(PBc + PPB + (row + 4) * RB + co * 2) = pack_bf(l0, l1);
                }
            }
        }
}

constexpr int SMEM_W = PAIR_W + WTB + 16;
constexpr int SMEM_H = PAIR_H + WTB + 16;
static_assert(SMEM_W <= 227 * 1024, "smem W over limit");

extern "C" void kernel_launch(void* const* d_in, const int* in_sizes, int n_in,
                              void* d_out, int out_size) {
    const float* x  = (const float*)d_in[0];
    const float* wd = (const float*)d_in[1];
    const float* wu = (const float*)d_in[2];
    const float* wr = (const float*)d_in[3];
    const float* wl = (const float*)d_in[4];
    float* out = (float*)d_out;

    static u8* pbw = nullptr;
    static u8* pbh = nullptr;
    static u8* wt = nullptr;
    static float* fw = nullptr;
    static float* fh = nullptr;
    static bool init_done = false;
    if (!init_done) {
        cudaGetSymbolAddress((void**)&pbw, g_pbw);
        cudaGetSymbolAddress((void**)&pbh, g_pbh);
        cudaGetSymbolAddress((void**)&wt, g_wt);
        cudaGetSymbolAddress((void**)&fw, g_fw);
        cudaGetSymbolAddress((void**)&fh, g_fh);
        cudaFuncSetAttribute((const void*)step_mma<W_, ROWS_W, H_, 7, 256>,
                             cudaFuncAttributeMaxDynamicSharedMemorySize, SMEM_W);
        cudaFuncSetAttribute((const void*)step_mma<H_, ROWS_H, W_, 3, 128>,
                             cudaFuncAttributeMaxDynamicSharedMemorySize, SMEM_H);
        init_done = true;
    }

    prep_weights<<<512, 256>>>(wd, wu, wr, wl);
    zero_pads<<<1024, 256>>>();
    conv_in<<<dim3(7, 4, B_ * H_), dim3(32, 8)>>>(x);

    const size_t DSTR = (size_t)8 * WTB;
    const dim3 grid(8, B_);

    for (int h = 1; h < H_; ++h)
        step_mma<W_, ROWS_W, H_, 7, 256><<<grid, 256, SMEM_W>>>(
            fw, pbw, wt + 0 * DSTR, h - 1, h);
    for (int h = H_ - 2; h >= 0; --h)
        step_mma<W_, ROWS_W, H_, 7, 256><<<grid, 256, SMEM_W>>>(
            fw, pbw, wt + 1 * DSTR, h + 1, h);

    transition<<<B_ * H_, 256>>>();

    for (int w = 1; w < W_; ++w)
        step_mma<H_, ROWS_H, W_, 3, 128><<<grid, 128, SMEM_H>>>(
            fh, pbh, wt + 2 * DSTR, w - 1, w);
    for (int w = W_ - 2; w >= 0; --w)
        step_mma<H_, ROWS_H, W_, 3, 128><<<grid, 128, SMEM_H>>>(
            fh, pbh, wt + 3 * DSTR, w + 1, w);

    conv_out<<<dim3(7, 4, B_ * H_), dim3(32, 8)>>>(out);
}